// round 3
// baseline (speedup 1.0000x reference)
#include <cuda_runtime.h>

// ============================================================================
// MyGRU on GB300 — fp32 baseline v3
//   Kernel 1: init (h <- h0, reset barrier counter)
//   Kernel 2: precompute xz/xr/xh = x @ W^T + b   (tiled fp32 GEMM, dbl-buf)
//   Kernel 3: persistent recurrent kernel, 1024 steps, 2 grid barriers/step
// ============================================================================

#define S_LEN 1024
#define BATCH 64
#define IDIM  512
#define HDIM  512

#define GRID_R 128          // persistent CTAs (<= 148 SMs, all resident)
#define TPB_R  256
#define JPC    4            // hidden columns owned per CTA (512/128)
#define PADK   516          // U row stride in smem (conflict-free)
#define REDP   72           // reduction row stride in smem (conflict-free)
#define NQ     (HDIM/4)     // float4 quads per h row
#define HB     (HDIM*BATCH)

// -------- device scratch (allocation-free rule: __device__ globals) --------
__device__ float g_h[BATCH*HDIM];                       // current hidden state
__device__ float g_rh[BATCH*HDIM];                      // r (*) h
__device__ float g_xg[(size_t)S_LEN*3*HDIM*BATCH];      // [s][gate][j][b]
__device__ unsigned int g_bar;                          // grid barrier counter

__device__ __forceinline__ float fast_tanh(float x){
    float y;
    asm("tanh.approx.f32 %0, %1;" : "=f"(y) : "f"(x));
    return y;
}
__device__ __forceinline__ float fast_sigmoid(float x){
    return fmaf(fast_tanh(0.5f * x), 0.5f, 0.5f);
}
__device__ __forceinline__ void fma4(float& acc, float4 a, float4 b){
    acc = fmaf(a.x, b.x, acc);
    acc = fmaf(a.y, b.y, acc);
    acc = fmaf(a.z, b.z, acc);
    acc = fmaf(a.w, b.w, acc);
}

// ============================================================================
// init
// ============================================================================
__global__ void init_kernel(const float* __restrict__ h0){
    int idx = blockIdx.x * blockDim.x + threadIdx.x;
    if (idx < BATCH*HDIM) g_h[idx] = h0[idx];
    if (idx == 0) g_bar = 0u;
}

// ============================================================================
// precompute: g_xg[s][g][j][b] = sum_k x[s][b][k] * Wg[j][k] + bg[j]
// BM=64 (one s), BN=128 (one gate slice), BK=32, 256 thr, tile 4(m)x8(n),
// register double-buffered global loads, vectorized epilogue stores.
// ============================================================================
#define BM 64
#define BN 128
#define BK 32

__global__ void __launch_bounds__(256)
precompute_kernel(const float* __restrict__ x,
                  const float* __restrict__ Wz_w, const float* __restrict__ Wz_b,
                  const float* __restrict__ Wr_w, const float* __restrict__ Wr_b,
                  const float* __restrict__ Wh_w, const float* __restrict__ Wh_b)
{
    __shared__ __align__(16) float As[BK][BM + 4];   // [k][m]
    __shared__ __align__(16) float Bs[BK][BN + 4];   // [k][n]

    const int s  = blockIdx.x;                 // 0..1023  (BM == BATCH)
    const int n0 = blockIdx.y * BN;            // 0..1408
    const int gate = n0 / HDIM;                // BN divides 512 -> no straddle
    const int j0   = n0 % HDIM;

    const float* W;  const float* bias;
    if      (gate == 0) { W = Wz_w; bias = Wz_b; }
    else if (gate == 1) { W = Wr_w; bias = Wr_b; }
    else                { W = Wh_w; bias = Wh_b; }

    const int tid = threadIdx.x;
    const int tm  = tid & 15;      // 16 m-groups of 4
    const int tn  = tid >> 4;      // 16 n-groups of 8

    // load mappings
    const int am  = tid & 63;            // A: row m, quads akq, akq+4
    const int akq = tid >> 6;            // 0..3
    const int bn  = tid & 127;           // B: row n, quads bkq..bkq+3
    const int bkq = (tid >> 7) * 4;      // 0 or 4

    const float* xrow = x + (size_t)(s * BATCH + am) * IDIM;
    const float* wrow = W + (size_t)(j0 + bn) * IDIM;

    float acc[4][8];
    #pragma unroll
    for (int i = 0; i < 4; i++)
        #pragma unroll
        for (int j = 0; j < 8; j++) acc[i][j] = 0.0f;

    float4 aReg[2], bReg[4];
    // prologue: load tile kt=0 into registers
    #pragma unroll
    for (int t = 0; t < 2; t++)
        aReg[t] = *(const float4*)(xrow + (akq + t * 4) * 4);
    #pragma unroll
    for (int t = 0; t < 4; t++)
        bReg[t] = *(const float4*)(wrow + (bkq + t) * 4);

    for (int kt = 0; kt < IDIM; kt += BK) {
        // commit current registers to smem
        #pragma unroll
        for (int t = 0; t < 2; t++) {
            int kq = akq + t * 4;
            As[kq*4+0][am] = aReg[t].x; As[kq*4+1][am] = aReg[t].y;
            As[kq*4+2][am] = aReg[t].z; As[kq*4+3][am] = aReg[t].w;
        }
        #pragma unroll
        for (int t = 0; t < 4; t++) {
            int kq = bkq + t;
            Bs[kq*4+0][bn] = bReg[t].x; Bs[kq*4+1][bn] = bReg[t].y;
            Bs[kq*4+2][bn] = bReg[t].z; Bs[kq*4+3][bn] = bReg[t].w;
        }
        __syncthreads();

        // prefetch next tile while computing this one
        if (kt + BK < IDIM) {
            #pragma unroll
            for (int t = 0; t < 2; t++)
                aReg[t] = *(const float4*)(xrow + kt + BK + (akq + t * 4) * 4);
            #pragma unroll
            for (int t = 0; t < 4; t++)
                bReg[t] = *(const float4*)(wrow + kt + BK + (bkq + t) * 4);
        }

        #pragma unroll
        for (int k = 0; k < BK; k++) {
            float4 a  = *(const float4*)(&As[k][tm * 4]);
            float4 b0 = *(const float4*)(&Bs[k][tn * 8]);
            float4 b1 = *(const float4*)(&Bs[k][tn * 8 + 4]);
            float av[4] = {a.x, a.y, a.z, a.w};
            float bv[8] = {b0.x, b0.y, b0.z, b0.w, b1.x, b1.y, b1.z, b1.w};
            #pragma unroll
            for (int mi = 0; mi < 4; mi++)
                #pragma unroll
                for (int ni = 0; ni < 8; ni++)
                    acc[mi][ni] = fmaf(av[mi], bv[ni], acc[mi][ni]);
        }
        __syncthreads();
    }

    // epilogue: bias add + vectorized stores (b is contiguous per thread)
    const size_t base = (size_t)(s * 3 + gate) * HB;
    #pragma unroll
    for (int ni = 0; ni < 8; ni++) {
        int j = j0 + tn * 8 + ni;
        float bvv = bias[j];
        float4 v = make_float4(acc[0][ni] + bvv, acc[1][ni] + bvv,
                               acc[2][ni] + bvv, acc[3][ni] + bvv);
        *(float4*)&g_xg[base + (size_t)j * BATCH + tm * 4] = v;
    }
}

// ============================================================================
// recurrent persistent kernel
//   128 CTAs; CTA c owns j in [4c, 4c+4). Per step:
//     phase 1: z[:,Jc], r[:,Jc] from h @ {Uz,Ur}^T; write r*h to g_rh
//     (grid barrier)
//     phase 2: h~[:,Jc] from (r*h) @ Uh^T; h_new; write g_h + outputs
//     (grid barrier)
//   U rows (12 x 512) + own h-columns live in SMEM. g_xg prefetched at step
//   top. Cross-CTA traffic (g_h, g_rh broadcast) via __ldcg (L2).
// ============================================================================
__device__ __forceinline__ void grid_barrier(unsigned goal){
    __syncthreads();
    if (threadIdx.x == 0) {
        __threadfence();                 // publish this CTA's global writes
        atomicAdd(&g_bar, 1u);
        while (*((volatile unsigned*)&g_bar) < goal) { }
        __threadfence();
    }
    __syncthreads();
}

__global__ void __launch_bounds__(TPB_R, 1)
gru_recurrent(const float* __restrict__ Uz_w, const float* __restrict__ Uz_b,
              const float* __restrict__ Ur_w, const float* __restrict__ Ur_b,
              const float* __restrict__ Uh_w, const float* __restrict__ Uh_b,
              float* __restrict__ out)
{
    __shared__ __align__(16) float sU[12 * PADK];      // rows: 0-3 Uz, 4-7 Ur, 8-11 Uh
    __shared__ float sZ[JPC * BATCH];                  // z gate, local columns
    __shared__ float sH[JPC * BATCH];                  // own h columns [row][b]
    __shared__ float sRed[64 * REDP];                  // k-slice reduction
    __shared__ float sBias[12];

    const int tid = threadIdx.x;
    const int cta = blockIdx.x;
    const int j0  = cta * JPC;

    // ---- load this CTA's 12 U rows + biases into SMEM (once) ----
    for (int idx = tid; idx < 12 * HDIM; idx += TPB_R) {
        int row = idx >> 9;        // /512
        int k   = idx & 511;
        const float* src; int j;
        if      (row < 4) { src = Uz_w; j = j0 + row;     }
        else if (row < 8) { src = Ur_w; j = j0 + row - 4; }
        else              { src = Uh_w; j = j0 + row - 8; }
        sU[row * PADK + k] = src[(size_t)j * HDIM + k];
    }
    if (tid < 12) {
        int row = tid;
        if      (row < 4) sBias[row] = Uz_b[j0 + row];
        else if (row < 8) sBias[row] = Ur_b[j0 + row - 4];
        else              sBias[row] = Uh_b[j0 + row - 8];
    }
    // own h columns into SMEM (h0 already in g_h via init_kernel)
    if (tid < JPC * BATCH) {
        int row = tid >> 6;            // 0..3 (local j)
        int b   = tid & 63;
        sH[row * BATCH + b] = g_h[b * HDIM + (j0 + row)];
    }
    __syncthreads();

    // thread decomposition: warp = k-slice, lane = (bgroup, rowgroup)
    const int ks   = tid >> 5;        // 0..7  : k slice of 64 (16 quads)
    const int lane = tid & 31;
    const int bg   = lane >> 2;       // 0..7  : b = bg + 8*i
    const int rg   = lane & 3;        // 0..3  : row group
    const int kq0  = ks * 16;

    // epilogue output assignments (fixed per thread)
    const int e1_row0 = (tid * 2) >> 6;          // phase-1 out 0: 0..7
    const int e1_b0   = (tid * 2) & 63;
    const int e1_row1 = (tid * 2 + 1) >> 6;      // phase-1 out 1
    const int e1_b1   = (tid * 2 + 1) & 63;
    const int e2_row  = tid >> 6;                // phase-2 out: 0..3
    const int e2_b    = tid & 63;

    // g_xg addresses (gate g at step s: (s*3+g)*HB + j*BATCH + b)
    const size_t xg_off0 = (size_t)((e1_row0 < 4 ? 0 : 1)) * HB
                         + (size_t)(j0 + (e1_row0 & 3)) * BATCH + e1_b0;
    const size_t xg_off1 = (size_t)((e1_row1 < 4 ? 0 : 1)) * HB
                         + (size_t)(j0 + (e1_row1 & 3)) * BATCH + e1_b1;
    const size_t xg_off2 = (size_t)2 * HB
                         + (size_t)(j0 + e2_row) * BATCH + e2_b;

    const float4* hq  = (const float4*)g_h;
    const float4* rhq = (const float4*)g_rh;
    const float4* sU4 = (const float4*)sU;    // row stride PADK/4 = 129 quads

    unsigned goal = 0;

    for (int s = 0; s < S_LEN; s++) {
        const size_t sb = (size_t)s * 3 * HB;
        // ---- prefetch this step's xg values (read-once, streaming) ----
        float xg0 = __ldcs(&g_xg[sb + xg_off0]);
        float xg1 = __ldcs(&g_xg[sb + xg_off1]);
        float xg2 = __ldcs(&g_xg[sb + xg_off2]);

        // ================= phase 1: z and r =================
        float accz[8], accr[8];
        #pragma unroll
        for (int i = 0; i < 8; i++) { accz[i] = 0.0f; accr[i] = 0.0f; }

        const int rz = rg;        // Uz row
        const int rr = 4 + rg;    // Ur row
        #pragma unroll 4
        for (int q = 0; q < 16; q++) {
            int kq = kq0 + q;
            float4 uz = sU4[rz * 129 + kq];
            float4 ur = sU4[rr * 129 + kq];
            #pragma unroll
            for (int i = 0; i < 8; i++) {
                int b = bg + 8 * i;
                float4 h4 = __ldcg(&hq[b * NQ + kq]);
                fma4(accz[i], h4, uz);
                fma4(accr[i], h4, ur);
            }
        }
        #pragma unroll
        for (int i = 0; i < 8; i++) {
            int b = bg + 8 * i;
            sRed[(ks * 8 + rg)     * REDP + b] = accz[i];
            sRed[(ks * 8 + 4 + rg) * REDP + b] = accr[i];
        }
        __syncthreads();

        // reduce 512 outputs (8 rows x 64 b), 2 per thread
        {
            float v0 = 0.0f, v1 = 0.0f;
            #pragma unroll
            for (int kk = 0; kk < 8; kk++) {
                v0 += sRed[(kk * 8 + e1_row0) * REDP + e1_b0];
                v1 += sRed[(kk * 8 + e1_row1) * REDP + e1_b1];
            }
            v0 += sBias[e1_row0] + xg0;
            v1 += sBias[e1_row1] + xg1;
            // out 0
            if (e1_row0 < 4) {
                sZ[e1_row0 * BATCH + e1_b0] = fast_sigmoid(v0);
            } else {
                float r  = fast_sigmoid(v0);
                float hv = sH[(e1_row0 - 4) * BATCH + e1_b0];
                g_rh[e1_b0 * HDIM + (j0 + e1_row0 - 4)] = r * hv;
            }
            // out 1
            if (e1_row1 < 4) {
                sZ[e1_row1 * BATCH + e1_b1] = fast_sigmoid(v1);
            } else {
                float r  = fast_sigmoid(v1);
                float hv = sH[(e1_row1 - 4) * BATCH + e1_b1];
                g_rh[e1_b1 * HDIM + (j0 + e1_row1 - 4)] = r * hv;
            }
        }
        goal += GRID_R;
        grid_barrier(goal);

        // ================= phase 2: h~ and update =================
        float acch[8];
        #pragma unroll
        for (int i = 0; i < 8; i++) acch[i] = 0.0f;

        const int rh_row = 8 + rg;   // Uh row
        #pragma unroll 4
        for (int q = 0; q < 16; q++) {
            int kq = kq0 + q;
            float4 uh = sU4[rh_row * 129 + kq];
            #pragma unroll
            for (int i = 0; i < 8; i++) {
                int b = bg + 8 * i;
                float4 r4 = __ldcg(&rhq[b * NQ + kq]);
                fma4(acch[i], r4, uh);
            }
        }
        #pragma unroll
        for (int i = 0; i < 8; i++) {
            int b = bg + 8 * i;
            sRed[(ks * 4 + rg) * REDP + b] = acch[i];
        }
        __syncthreads();

        {
            float v = 0.0f;
            #pragma unroll
            for (int kk = 0; kk < 8; kk++) v += sRed[(kk * 4 + e2_row) * REDP + e2_b];
            int j = j0 + e2_row;
            float ht   = fast_tanh(v + sBias[8 + e2_row] + xg2);
            float z    = sZ[e2_row * BATCH + e2_b];
            float hold = sH[e2_row * BATCH + e2_b];
            float hnew = fmaf(z, ht - hold, hold);   // (1-z)h + z*h~
            sH[e2_row * BATCH + e2_b] = hnew;
            g_h[e2_b * HDIM + j] = hnew;
            __stcs(&out[((size_t)s * BATCH + e2_b) * HDIM + j], hnew);
            if (s == S_LEN - 1)
                out[(size_t)S_LEN * BATCH * HDIM + (size_t)e2_b * HDIM + j] = hnew;
        }
        goal += GRID_R;
        grid_barrier(goal);
    }
}

// ============================================================================
// launch
// ============================================================================
extern "C" void kernel_launch(void* const* d_in, const int* in_sizes, int n_in,
                              void* d_out, int out_size)
{
    const float* x    = (const float*)d_in[0];
    const float* h0   = (const float*)d_in[1];
    const float* Wz_w = (const float*)d_in[2];
    const float* Wz_b = (const float*)d_in[3];
    const float* Uz_w = (const float*)d_in[4];
    const float* Uz_b = (const float*)d_in[5];
    const float* Wr_w = (const float*)d_in[6];
    const float* Wr_b = (const float*)d_in[7];
    const float* Ur_w = (const float*)d_in[8];
    const float* Ur_b = (const float*)d_in[9];
    const float* Wh_w = (const float*)d_in[10];
    const float* Wh_b = (const float*)d_in[11];
    const float* Uh_w = (const float*)d_in[12];
    const float* Uh_b = (const float*)d_in[13];
    float* out = (float*)d_out;

    init_kernel<<<(BATCH*HDIM + 255)/256, 256>>>(h0);

    dim3 pgrid(S_LEN, (3 * HDIM) / BN);      // (1024, 12)
    precompute_kernel<<<pgrid, 256>>>(x, Wz_w, Wz_b, Wr_w, Wr_b, Wh_w, Wh_b);

    gru_recurrent<<<GRID_R, TPB_R>>>(Uz_w, Uz_b, Ur_w, Ur_b, Uh_w, Uh_b, out);
}

// round 10
// speedup vs baseline: 1.4327x; 1.4327x over previous
#include <cuda_runtime.h>

// ============================================================================
// MyGRU on GB300 — v4.2: SMEM-staged recurrence (kills 4x redundant L2 reads)
//   Kernel 1: init
//   Kernel 2: precompute xz/xr/xh = x @ W^T + b  (grid swapped for L2 reuse)
//   Kernel 3: persistent recurrence, h/rh staged via SMEM, 2 barriers/step
// ============================================================================

#define S_LEN 1024
#define BATCH 64
#define IDIM  512
#define HDIM  512

#define GRID_R 128          // persistent CTAs (<= 148 SMs, all resident)
#define TPB_R  256
#define JPC    4            // hidden columns owned per CTA (512/128)
#define PADK   516          // U row stride in smem floats (conflict-free)
#define REDP   72           // reduction row stride in smem (conflict-free)
#define HQ     128          // quads per h row
#define HQP    129          // padded quad stride for staged h (conflict-free)
#define HB     (HDIM*BATCH)

// dynamic smem: staged h / rh buffer, 64 rows x 129 quads = 132096 B
#define DYN_BYTES (BATCH * HQP * 16)

// -------- device scratch (allocation-free rule: __device__ globals) --------
__device__ float g_h[BATCH*HDIM];                       // current hidden state
__device__ float g_rh[BATCH*HDIM];                      // r (*) h
__device__ float g_xg[(size_t)S_LEN*3*HDIM*BATCH];      // [s][gate][j][b]
__device__ unsigned int g_bar;                          // grid barrier counter

__device__ __forceinline__ float fast_tanh(float x){
    float y;
    asm("tanh.approx.f32 %0, %1;" : "=f"(y) : "f"(x));
    return y;
}
__device__ __forceinline__ float fast_sigmoid(float x){
    return fmaf(fast_tanh(0.5f * x), 0.5f, 0.5f);
}
__device__ __forceinline__ void fma4(float& acc, float4 a, float4 b){
    acc = fmaf(a.x, b.x, acc);
    acc = fmaf(a.y, b.y, acc);
    acc = fmaf(a.z, b.z, acc);
    acc = fmaf(a.w, b.w, acc);
}

// ============================================================================
// init
// ============================================================================
__global__ void init_kernel(const float* __restrict__ h0){
    int idx = blockIdx.x * blockDim.x + threadIdx.x;
    if (idx < BATCH*HDIM) g_h[idx] = h0[idx];
    if (idx == 0) g_bar = 0u;
}

// ============================================================================
// precompute: g_xg[s][g][j][b] = sum_k x[s][b][k] * Wg[j][k] + bg[j]
// BM=64 (one s), BN=128 (one gate slice), BK=32, 256 thr, tile 4(m)x8(n).
// grid = (12 n-blocks, 1024 s): adjacent bids share the x s-tile -> L2 reuse.
// ============================================================================
#define BM 64
#define BN 128
#define BK 32

__global__ void __launch_bounds__(256)
precompute_kernel(const float* __restrict__ x,
                  const float* __restrict__ Wz_w, const float* __restrict__ Wz_b,
                  const float* __restrict__ Wr_w, const float* __restrict__ Wr_b,
                  const float* __restrict__ Wh_w, const float* __restrict__ Wh_b)
{
    __shared__ __align__(16) float As[BK][BM + 4];   // [k][m]
    __shared__ __align__(16) float Bs[BK][BN + 4];   // [k][n]

    const int s  = blockIdx.y;                 // 0..1023  (BM == BATCH)
    const int n0 = blockIdx.x * BN;            // 0..1408
    const int gate = n0 / HDIM;                // BN divides 512 -> no straddle
    const int j0   = n0 % HDIM;

    const float* W;  const float* bias;
    if      (gate == 0) { W = Wz_w; bias = Wz_b; }
    else if (gate == 1) { W = Wr_w; bias = Wr_b; }
    else                { W = Wh_w; bias = Wh_b; }

    const int tid = threadIdx.x;
    const int tm  = tid & 15;      // 16 m-groups of 4
    const int tn  = tid >> 4;      // 16 n-groups of 8

    // load mappings
    const int am  = tid & 63;            // A: row m, quads akq, akq+4
    const int akq = tid >> 6;            // 0..3
    const int bn  = tid & 127;           // B: row n, quads bkq..bkq+3
    const int bkq = (tid >> 7) * 4;      // 0 or 4

    const float* xrow = x + (size_t)(s * BATCH + am) * IDIM;
    const float* wrow = W + (size_t)(j0 + bn) * IDIM;

    float acc[4][8];
    #pragma unroll
    for (int i = 0; i < 4; i++)
        #pragma unroll
        for (int j = 0; j < 8; j++) acc[i][j] = 0.0f;

    float4 aReg[2], bReg[4];
    #pragma unroll
    for (int t = 0; t < 2; t++)
        aReg[t] = *(const float4*)(xrow + (akq + t * 4) * 4);
    #pragma unroll
    for (int t = 0; t < 4; t++)
        bReg[t] = *(const float4*)(wrow + (bkq + t) * 4);

    for (int kt = 0; kt < IDIM; kt += BK) {
        #pragma unroll
        for (int t = 0; t < 2; t++) {
            int kq = akq + t * 4;
            As[kq*4+0][am] = aReg[t].x; As[kq*4+1][am] = aReg[t].y;
            As[kq*4+2][am] = aReg[t].z; As[kq*4+3][am] = aReg[t].w;
        }
        #pragma unroll
        for (int t = 0; t < 4; t++) {
            int kq = bkq + t;
            Bs[kq*4+0][bn] = bReg[t].x; Bs[kq*4+1][bn] = bReg[t].y;
            Bs[kq*4+2][bn] = bReg[t].z; Bs[kq*4+3][bn] = bReg[t].w;
        }
        __syncthreads();

        if (kt + BK < IDIM) {
            #pragma unroll
            for (int t = 0; t < 2; t++)
                aReg[t] = *(const float4*)(xrow + kt + BK + (akq + t * 4) * 4);
            #pragma unroll
            for (int t = 0; t < 4; t++)
                bReg[t] = *(const float4*)(wrow + kt + BK + (bkq + t) * 4);
        }

        #pragma unroll
        for (int k = 0; k < BK; k++) {
            float4 a  = *(const float4*)(&As[k][tm * 4]);
            float4 b0 = *(const float4*)(&Bs[k][tn * 8]);
            float4 b1 = *(const float4*)(&Bs[k][tn * 8 + 4]);
            float av[4] = {a.x, a.y, a.z, a.w};
            float bv[8] = {b0.x, b0.y, b0.z, b0.w, b1.x, b1.y, b1.z, b1.w};
            #pragma unroll
            for (int mi = 0; mi < 4; mi++)
                #pragma unroll
                for (int ni = 0; ni < 8; ni++)
                    acc[mi][ni] = fmaf(av[mi], bv[ni], acc[mi][ni]);
        }
        __syncthreads();
    }

    // epilogue: bias add + vectorized stores (b contiguous per thread)
    const size_t base = (size_t)(s * 3 + gate) * HB;
    #pragma unroll
    for (int ni = 0; ni < 8; ni++) {
        int j = j0 + tn * 8 + ni;
        float bvv = bias[j];
        float4 v = make_float4(acc[0][ni] + bvv, acc[1][ni] + bvv,
                               acc[2][ni] + bvv, acc[3][ni] + bvv);
        *(float4*)&g_xg[base + (size_t)j * BATCH + tm * 4] = v;
    }
}

// ============================================================================
// recurrent persistent kernel
//   Per phase, each warp stages its own k-slice of h (or rh) from L2 into
//   dynamic SMEM exactly once (no redundancy, warp-local so no CTA sync),
//   then FMAs read SMEM with broadcast. L2 traffic: 16 MB/phase chip-wide.
// ============================================================================
__device__ __forceinline__ void grid_barrier(unsigned goal){
    __syncthreads();
    if (threadIdx.x == 0) {
        __threadfence();                 // publish this CTA's global writes
        atomicAdd(&g_bar, 1u);
        while (*((volatile unsigned*)&g_bar) < goal) { }
        __threadfence();
    }
    __syncthreads();
}

__global__ void __launch_bounds__(TPB_R, 1)
gru_recurrent(const float* __restrict__ Uz_w, const float* __restrict__ Uz_b,
              const float* __restrict__ Ur_w, const float* __restrict__ Ur_b,
              const float* __restrict__ Uh_w, const float* __restrict__ Uh_b,
              float* __restrict__ out)
{
    extern __shared__ __align__(16) float4 sStage[];   // [64][HQP] staged h / rh

    __shared__ __align__(16) float sU[12 * PADK];      // 0-3 Uz, 4-7 Ur, 8-11 Uh
    __shared__ float sZ[JPC * BATCH];                  // z gate, local columns
    __shared__ float sHown[JPC * BATCH];               // own h columns [row][b]
    __shared__ float sRed[64 * REDP];                  // k-slice reduction
    __shared__ float sBias[12];

    const int tid = threadIdx.x;
    const int cta = blockIdx.x;
    const int j0  = cta * JPC;

    // ---- load this CTA's 12 U rows + biases into SMEM (once) ----
    for (int idx = tid; idx < 12 * HDIM; idx += TPB_R) {
        int row = idx >> 9;        // /512
        int k   = idx & 511;
        const float* src; int j;
        if      (row < 4) { src = Uz_w; j = j0 + row;     }
        else if (row < 8) { src = Ur_w; j = j0 + row - 4; }
        else              { src = Uh_w; j = j0 + row - 8; }
        sU[row * PADK + k] = src[(size_t)j * HDIM + k];
    }
    if (tid < 12) {
        int row = tid;
        if      (row < 4) sBias[row] = Uz_b[j0 + row];
        else if (row < 8) sBias[row] = Ur_b[j0 + row - 4];
        else              sBias[row] = Uh_b[j0 + row - 8];
    }
    if (tid < JPC * BATCH) {
        int row = tid >> 6;            // 0..3 (local j)
        int b   = tid & 63;
        sHown[row * BATCH + b] = g_h[b * HDIM + (j0 + row)];
    }
    __syncthreads();

    // thread decomposition: warp = k-slice, lane = (bgroup, rowgroup)
    const int ks   = tid >> 5;        // 0..7  : k slice of 64 floats (16 quads)
    const int lane = tid & 31;
    const int bg   = lane >> 2;       // 0..7  : b = bg + 8*i
    const int rg   = lane & 3;        // 0..3  : row group
    const int kq0  = ks * 16;

    // staging map: each lane owns quad (kq0+st_q) of b-rows st_b0, st_b0+2, ...
    const int st_q  = lane & 15;                 // quad within slice
    const int st_b0 = lane >> 4;                 // 0..1
    const int st_sm0 = st_b0 * HQP + kq0 + st_q; // smem quad index, step 2*HQP
    const int st_gm0 = st_b0 * HQ  + kq0 + st_q; // gmem quad index, step 2*HQ

    // epilogue output assignments (fixed per thread)
    const int e1_row0 = (tid * 2) >> 6;          // phase-1 out 0: 0..7
    const int e1_b0   = (tid * 2) & 63;
    const int e1_row1 = (tid * 2 + 1) >> 6;      // phase-1 out 1
    const int e1_b1   = (tid * 2 + 1) & 63;
    const int e2_row  = tid >> 6;                // phase-2 out: 0..3
    const int e2_b    = tid & 63;

    const size_t xg_off0 = (size_t)((e1_row0 < 4 ? 0 : 1)) * HB
                         + (size_t)(j0 + (e1_row0 & 3)) * BATCH + e1_b0;
    const size_t xg_off1 = (size_t)((e1_row1 < 4 ? 0 : 1)) * HB
                         + (size_t)(j0 + (e1_row1 & 3)) * BATCH + e1_b1;
    const size_t xg_off2 = (size_t)2 * HB
                         + (size_t)(j0 + e2_row) * BATCH + e2_b;

    const float4* hq  = (const float4*)g_h;
    const float4* rhq = (const float4*)g_rh;
    const float4* sU4 = (const float4*)sU;    // row stride PADK/4 = 129 quads

    unsigned goal = 0;

    for (int s = 0; s < S_LEN; s++) {
        const size_t sb = (size_t)s * 3 * HB;
        float xg0 = __ldcs(&g_xg[sb + xg_off0]);
        float xg1 = __ldcs(&g_xg[sb + xg_off1]);
        float xg2 = __ldcs(&g_xg[sb + xg_off2]);

        // ---- stage h: warp ks loads quads [kq0, kq0+16) for all 64 b ----
        #pragma unroll
        for (int i = 0; i < 32; i++) {
            sStage[st_sm0 + i * (2 * HQP)] = __ldcg(&hq[st_gm0 + i * (2 * HQ)]);
        }
        __syncwarp();

        // ================= phase 1: z and r =================
        float accz[8], accr[8];
        #pragma unroll
        for (int i = 0; i < 8; i++) { accz[i] = 0.0f; accr[i] = 0.0f; }

        const int rz = rg;        // Uz row
        const int rr = 4 + rg;    // Ur row
        #pragma unroll 4
        for (int q = 0; q < 16; q++) {
            int kq = kq0 + q;
            float4 uz = sU4[rz * 129 + kq];
            float4 ur = sU4[rr * 129 + kq];
            #pragma unroll
            for (int i = 0; i < 8; i++) {
                int b = bg + 8 * i;
                float4 h4 = sStage[b * HQP + kq];
                fma4(accz[i], h4, uz);
                fma4(accr[i], h4, ur);
            }
        }
        #pragma unroll
        for (int i = 0; i < 8; i++) {
            int b = bg + 8 * i;
            sRed[(ks * 8 + rg)     * REDP + b] = accz[i];
            sRed[(ks * 8 + 4 + rg) * REDP + b] = accr[i];
        }
        __syncthreads();

        // reduce 512 outputs (8 rows x 64 b), 2 per thread
        {
            float v0 = 0.0f, v1 = 0.0f;
            #pragma unroll
            for (int kk = 0; kk < 8; kk++) {
                v0 += sRed[(kk * 8 + e1_row0) * REDP + e1_b0];
                v1 += sRed[(kk * 8 + e1_row1) * REDP + e1_b1];
            }
            v0 += sBias[e1_row0] + xg0;
            v1 += sBias[e1_row1] + xg1;
            if (e1_row0 < 4) {
                sZ[e1_row0 * BATCH + e1_b0] = fast_sigmoid(v0);
            } else {
                float r  = fast_sigmoid(v0);
                float hv = sHown[(e1_row0 - 4) * BATCH + e1_b0];
                g_rh[e1_b0 * HDIM + (j0 + e1_row0 - 4)] = r * hv;
            }
            if (e1_row1 < 4) {
                sZ[e1_row1 * BATCH + e1_b1] = fast_sigmoid(v1);
            } else {
                float r  = fast_sigmoid(v1);
                float hv = sHown[(e1_row1 - 4) * BATCH + e1_b1];
                g_rh[e1_b1 * HDIM + (j0 + e1_row1 - 4)] = r * hv;
            }
        }
        goal += GRID_R;
        grid_barrier(goal);

        // ---- stage rh (overwrites sStage; safe: barrier synced all reads) ----
        #pragma unroll
        for (int i = 0; i < 32; i++) {
            sStage[st_sm0 + i * (2 * HQP)] = __ldcg(&rhq[st_gm0 + i * (2 * HQ)]);
        }
        __syncwarp();

        // ================= phase 2: h~ and update =================
        float acch[8];
        #pragma unroll
        for (int i = 0; i < 8; i++) acch[i] = 0.0f;

        const int rh_row = 8 + rg;   // Uh row
        #pragma unroll 4
        for (int q = 0; q < 16; q++) {
            int kq = kq0 + q;
            float4 uh = sU4[rh_row * 129 + kq];
            #pragma unroll
            for (int i = 0; i < 8; i++) {
                int b = bg + 8 * i;
                float4 r4 = sStage[b * HQP + kq];
                fma4(acch[i], r4, uh);
            }
        }
        #pragma unroll
        for (int i = 0; i < 8; i++) {
            int b = bg + 8 * i;
            sRed[(ks * 4 + rg) * REDP + b] = acch[i];
        }
        __syncthreads();

        {
            float v = 0.0f;
            #pragma unroll
            for (int kk = 0; kk < 8; kk++) v += sRed[(kk * 4 + e2_row) * REDP + e2_b];
            int j = j0 + e2_row;
            float ht   = fast_tanh(v + sBias[8 + e2_row] + xg2);
            float z    = sZ[e2_row * BATCH + e2_b];
            float hold = sHown[e2_row * BATCH + e2_b];
            float hnew = fmaf(z, ht - hold, hold);   // (1-z)h + z*h~
            sHown[e2_row * BATCH + e2_b] = hnew;
            g_h[e2_b * HDIM + j] = hnew;
            __stcs(&out[((size_t)s * BATCH + e2_b) * HDIM + j], hnew);
            if (s == S_LEN - 1)
                out[(size_t)S_LEN * BATCH * HDIM + (size_t)e2_b * HDIM + j] = hnew;
        }
        goal += GRID_R;
        grid_barrier(goal);
    }
}

// ============================================================================
// launch
// ============================================================================
extern "C" void kernel_launch(void* const* d_in, const int* in_sizes, int n_in,
                              void* d_out, int out_size)
{
    const float* x    = (const float*)d_in[0];
    const float* h0   = (const float*)d_in[1];
    const float* Wz_w = (const float*)d_in[2];
    const float* Wz_b = (const float*)d_in[3];
    const float* Uz_w = (const float*)d_in[4];
    const float* Uz_b = (const float*)d_in[5];
    const float* Wr_w = (const float*)d_in[6];
    const float* Wr_b = (const float*)d_in[7];
    const float* Ur_w = (const float*)d_in[8];
    const float* Ur_b = (const float*)d_in[9];
    const float* Wh_w = (const float*)d_in[10];
    const float* Wh_b = (const float*)d_in[11];
    const float* Uh_w = (const float*)d_in[12];
    const float* Uh_b = (const float*)d_in[13];
    float* out = (float*)d_out;

    // idempotent attribute set; not a stream op, safe under graph capture
    cudaFuncSetAttribute(gru_recurrent,
                         cudaFuncAttributeMaxDynamicSharedMemorySize, DYN_BYTES);

    init_kernel<<<(BATCH*HDIM + 255)/256, 256>>>(h0);

    dim3 pgrid((3 * HDIM) / BN, S_LEN);      // (12, 1024): same-s blocks adjacent
    precompute_kernel<<<pgrid, 256>>>(x, Wz_w, Wz_b, Wr_w, Wr_b, Wh_w, Wh_b);

    gru_recurrent<<<GRID_R, TPB_R, DYN_BYTES>>>(Uz_w, Uz_b, Ur_w, Ur_b,
                                                Uh_w, Uh_b, out);
}